// round 1
// baseline (speedup 1.0000x reference)
#include <cuda_runtime.h>
#include <cuda_bf16.h>
#include <cstdint>

// ScaleLayer: y[b,d] = x[b,d] * exp(diag[d]);  second output = raw diag.
// x: [16384, 4096] fp32 row-major; diag: [4096] fp32.
// Strategy: precompute exp(diag) into a __device__ scratch table (4096 MUFU
// ops total instead of 67M), then a pure streaming float4 multiply kernel.
// This is DRAM-roofline bound: 512 MiB traffic -> ~75-85 us on GB300.

#define D_DIM 4096
#define B_DIM 16384

__device__ float g_ediag[D_DIM];

// Prologue: exp(diag) -> g_ediag, and echo raw diag into the tail of d_out
// (the reference returns (out, diag) as a tuple).
__global__ void prep_kernel(const float* __restrict__ diag,
                            float* __restrict__ out_tail,
                            int write_tail) {
    int i = blockIdx.x * blockDim.x + threadIdx.x;
    if (i < D_DIM) {
        float d = diag[i];
        g_ediag[i] = expf(d);
        if (write_tail) out_tail[i] = d;
    }
}

// Main streaming kernel: float4-vectorized broadcast multiply.
// Total float4 elements: 16384*4096/4 = 16,777,216.
// exp table (16 KB) stays resident in L1; only x-read + y-write hit DRAM.
__global__ void __launch_bounds__(256)
scale_kernel(const float4* __restrict__ x, float4* __restrict__ y) {
    const int total4 = (B_DIM * D_DIM) / 4;        // 16,777,216
    const int stride = gridDim.x * blockDim.x;
    const float4* __restrict__ ed =
        reinterpret_cast<const float4*>(g_ediag);  // 1024 float4 columns

    int j = blockIdx.x * blockDim.x + threadIdx.x;

    // 4-way unrolled grid-stride: front-batch 4 independent LDG.128 for MLP.
    for (; j + 3 * stride < total4; j += 4 * stride) {
        int j0 = j, j1 = j + stride, j2 = j + 2 * stride, j3 = j + 3 * stride;
        float4 v0 = x[j0];
        float4 v1 = x[j1];
        float4 v2 = x[j2];
        float4 v3 = x[j3];
        float4 e0 = ed[j0 & (D_DIM / 4 - 1)];
        float4 e1 = ed[j1 & (D_DIM / 4 - 1)];
        float4 e2 = ed[j2 & (D_DIM / 4 - 1)];
        float4 e3 = ed[j3 & (D_DIM / 4 - 1)];
        v0.x *= e0.x; v0.y *= e0.y; v0.z *= e0.z; v0.w *= e0.w;
        v1.x *= e1.x; v1.y *= e1.y; v1.z *= e1.z; v1.w *= e1.w;
        v2.x *= e2.x; v2.y *= e2.y; v2.z *= e2.z; v2.w *= e2.w;
        v3.x *= e3.x; v3.y *= e3.y; v3.z *= e3.z; v3.w *= e3.w;
        y[j0] = v0;
        y[j1] = v1;
        y[j2] = v2;
        y[j3] = v3;
    }
    for (; j < total4; j += stride) {
        float4 v = x[j];
        float4 e = ed[j & (D_DIM / 4 - 1)];
        v.x *= e.x; v.y *= e.y; v.z *= e.z; v.w *= e.w;
        y[j] = v;
    }
}

extern "C" void kernel_launch(void* const* d_in, const int* in_sizes, int n_in,
                              void* d_out, int out_size) {
    const float* x    = (const float*)d_in[0];
    const float* diag = (const float*)d_in[1];
    float* out = (float*)d_out;

    const long long n_main = (long long)B_DIM * D_DIM;
    const int write_tail = (out_size > n_main) ? 1 : 0;

    // Prologue: 4096 threads -> exp table + diag echo.
    prep_kernel<<<(D_DIM + 255) / 256, 256>>>(diag, out + n_main, write_tail);

    // Main: 16,777,216 float4 / (256 thr * 4 unroll) = 16384 CTAs.
    const int total4 = (B_DIM * D_DIM) / 4;
    int grid = total4 / (256 * 4);  // 16384
    scale_kernel<<<grid, 256>>>((const float4*)x, (float4*)out);
}

// round 2
// speedup vs baseline: 1.0008x; 1.0008x over previous
#include <cuda_runtime.h>
#include <cuda_bf16.h>
#include <cstdint>

// ScaleLayer: y[b,d] = x[b,d] * exp(diag[d]);  second output = raw diag.
// x: [16384, 4096] fp32 row-major; diag: [4096] fp32.
//
// Single-kernel design: each thread owns ONE float4 column group and streams
// down rows. exp(diag) for its 4 columns is computed once into registers
// (2M MUFU total chip-wide, hidden under first loads) -- no prologue kernel,
// no __device__ table, no launch serialization. Pure DRAM-roofline stream:
// 512 MiB traffic. __ldcs/__stcs evict-first hints (zero reuse).

#define D_DIM   4096
#define B_DIM   16384
#define COLS4   (D_DIM / 4)          // 1024 float4 columns per row
#define THREADS 256
#define COL_BLOCKS (COLS4 / THREADS) // 4 CTAs span the row width
#define ROW_BLOCKS 1024              // row tiling
#define ROWS_PER_THREAD (B_DIM / ROW_BLOCKS)  // 16

__global__ void __launch_bounds__(THREADS)
scale_kernel(const float4* __restrict__ x,
             const float4* __restrict__ diag4,
             float4* __restrict__ y,
             float4* __restrict__ tail,   // d_out + B*D (raw diag echo), may be null
             int write_tail) {
    const int colBlock = blockIdx.x & (COL_BLOCKS - 1);
    const int rowBlock = blockIdx.x >> 2;                // 0..1023
    const int col4 = colBlock * THREADS + threadIdx.x;   // 0..1023

    // Per-thread exp of its 4 diag entries -- once, into registers.
    float4 d = diag4[col4];
    if (write_tail && rowBlock == 0) tail[col4] = d;     // echo raw diag
    float4 e;
    e.x = expf(d.x);
    e.y = expf(d.y);
    e.z = expf(d.z);
    e.w = expf(d.w);

    const int r0 = rowBlock * ROWS_PER_THREAD;
    const float4* __restrict__ xp = x + (size_t)r0 * COLS4 + col4;
    float4*       __restrict__ yp = y + (size_t)r0 * COLS4 + col4;

    // 16 rows per thread: 4 outer iterations x 4-row unrolled batches.
    // Front-batched __ldcs x4 gives MLP=4 per thread; consecutive threads
    // read consecutive float4 within a row -> perfectly coalesced 128B lines.
    #pragma unroll
    for (int o = 0; o < ROWS_PER_THREAD / 4; o++) {
        const float4* xb = xp + (size_t)(o * 4) * COLS4;
        float4*       yb = yp + (size_t)(o * 4) * COLS4;
        float4 v0 = __ldcs(xb + 0 * COLS4);
        float4 v1 = __ldcs(xb + 1 * COLS4);
        float4 v2 = __ldcs(xb + 2 * COLS4);
        float4 v3 = __ldcs(xb + 3 * COLS4);
        v0.x *= e.x; v0.y *= e.y; v0.z *= e.z; v0.w *= e.w;
        v1.x *= e.x; v1.y *= e.y; v1.z *= e.z; v1.w *= e.w;
        v2.x *= e.x; v2.y *= e.y; v2.z *= e.z; v2.w *= e.w;
        v3.x *= e.x; v3.y *= e.y; v3.z *= e.z; v3.w *= e.w;
        __stcs(yb + 0 * COLS4, v0);
        __stcs(yb + 1 * COLS4, v1);
        __stcs(yb + 2 * COLS4, v2);
        __stcs(yb + 3 * COLS4, v3);
    }
}

extern "C" void kernel_launch(void* const* d_in, const int* in_sizes, int n_in,
                              void* d_out, int out_size) {
    const float* x    = (const float*)d_in[0];
    const float* diag = (const float*)d_in[1];
    float* out = (float*)d_out;

    const long long n_main = (long long)B_DIM * D_DIM;
    const int write_tail = (out_size > n_main) ? 1 : 0;

    const int grid = COL_BLOCKS * ROW_BLOCKS;  // 4096 CTAs
    scale_kernel<<<grid, THREADS>>>((const float4*)x,
                                    (const float4*)diag,
                                    (float4*)out,
                                    (float4*)(out + n_main),
                                    write_tail);
}

// round 3
// speedup vs baseline: 1.0034x; 1.0027x over previous
#include <cuda_runtime.h>
#include <cuda_bf16.h>
#include <cstdint>

// ScaleLayer: y[b,d] = x[b,d] * exp(diag[d]);  second output = raw diag.
// x: [16384, 4096] fp32 row-major; diag: [4096] fp32.
//
// R3: back to the R1 linear grid-stride streaming structure (best measured:
// 76.0us @ 80.7% DRAM), plus __ldcs/__stcs evict-first hints and MLP=8
// front-batched LDG.128 per thread. exp(diag) precomputed once into a
// __device__ table (prologue kernel measured free; table reads hit L1).

#define D_DIM 4096
#define B_DIM 16384

__device__ float g_ediag[D_DIM];

__global__ void prep_kernel(const float* __restrict__ diag,
                            float* __restrict__ out_tail,
                            int write_tail) {
    int i = blockIdx.x * blockDim.x + threadIdx.x;
    if (i < D_DIM) {
        float d = diag[i];
        g_ediag[i] = expf(d);
        if (write_tail) out_tail[i] = d;
    }
}

__global__ void __launch_bounds__(256)
scale_kernel(const float4* __restrict__ x, float4* __restrict__ y) {
    const int total4 = (B_DIM * D_DIM) / 4;        // 16,777,216
    const int stride = gridDim.x * blockDim.x;     // total4 / 8
    const float4* __restrict__ ed =
        reinterpret_cast<const float4*>(g_ediag);  // 1024 float4 columns

    int j = blockIdx.x * blockDim.x + threadIdx.x;

    // 8-way unrolled grid-stride: 8 independent streaming LDG.128 in flight
    // per thread before any store. Exact fit: total4 == 8 * stride when
    // grid = total4/(256*8), so the loop body runs exactly once per thread
    // and no tail is needed -- but keep it general for safety.
    for (; j + 7 * stride < total4; j += 8 * stride) {
        int j0 = j;
        int j1 = j + stride;
        int j2 = j + 2 * stride;
        int j3 = j + 3 * stride;
        int j4 = j + 4 * stride;
        int j5 = j + 5 * stride;
        int j6 = j + 6 * stride;
        int j7 = j + 7 * stride;
        float4 v0 = __ldcs(x + j0);
        float4 v1 = __ldcs(x + j1);
        float4 v2 = __ldcs(x + j2);
        float4 v3 = __ldcs(x + j3);
        float4 v4 = __ldcs(x + j4);
        float4 v5 = __ldcs(x + j5);
        float4 v6 = __ldcs(x + j6);
        float4 v7 = __ldcs(x + j7);
        float4 e0 = ed[j0 & (D_DIM / 4 - 1)];
        float4 e1 = ed[j1 & (D_DIM / 4 - 1)];
        float4 e2 = ed[j2 & (D_DIM / 4 - 1)];
        float4 e3 = ed[j3 & (D_DIM / 4 - 1)];
        float4 e4 = ed[j4 & (D_DIM / 4 - 1)];
        float4 e5 = ed[j5 & (D_DIM / 4 - 1)];
        float4 e6 = ed[j6 & (D_DIM / 4 - 1)];
        float4 e7 = ed[j7 & (D_DIM / 4 - 1)];
        v0.x *= e0.x; v0.y *= e0.y; v0.z *= e0.z; v0.w *= e0.w;
        v1.x *= e1.x; v1.y *= e1.y; v1.z *= e1.z; v1.w *= e1.w;
        v2.x *= e2.x; v2.y *= e2.y; v2.z *= e2.z; v2.w *= e2.w;
        v3.x *= e3.x; v3.y *= e3.y; v3.z *= e3.z; v3.w *= e3.w;
        v4.x *= e4.x; v4.y *= e4.y; v4.z *= e4.z; v4.w *= e4.w;
        v5.x *= e5.x; v5.y *= e5.y; v5.z *= e5.z; v5.w *= e5.w;
        v6.x *= e6.x; v6.y *= e6.y; v6.z *= e6.z; v6.w *= e6.w;
        v7.x *= e7.x; v7.y *= e7.y; v7.z *= e7.z; v7.w *= e7.w;
        __stcs(y + j0, v0);
        __stcs(y + j1, v1);
        __stcs(y + j2, v2);
        __stcs(y + j3, v3);
        __stcs(y + j4, v4);
        __stcs(y + j5, v5);
        __stcs(y + j6, v6);
        __stcs(y + j7, v7);
    }
    for (; j < total4; j += stride) {
        float4 v = __ldcs(x + j);
        float4 e = ed[j & (D_DIM / 4 - 1)];
        v.x *= e.x; v.y *= e.y; v.z *= e.z; v.w *= e.w;
        __stcs(y + j, v);
    }
}

extern "C" void kernel_launch(void* const* d_in, const int* in_sizes, int n_in,
                              void* d_out, int out_size) {
    const float* x    = (const float*)d_in[0];
    const float* diag = (const float*)d_in[1];
    float* out = (float*)d_out;

    const long long n_main = (long long)B_DIM * D_DIM;
    const int write_tail = (out_size > n_main) ? 1 : 0;

    prep_kernel<<<(D_DIM + 255) / 256, 256>>>(diag, out + n_main, write_tail);

    const int total4 = (B_DIM * D_DIM) / 4;
    int grid = total4 / (256 * 8);  // 8192 CTAs, exact cover
    scale_kernel<<<grid, 256>>>((const float4*)x, (float4*)out);
}